// round 13
// baseline (speedup 1.0000x reference)
#include <cuda_runtime.h>
#include <cuda_fp16.h>
#include <math.h>
#include <stdint.h>

// Fused LSTM cell, fp16 mma.sync m16n8k16 (f32 accum) + ldmatrix.
// R13 = R12 chassis + cvt/GEMM OVERLAP:
//   - cvt rewritten k-major, publishes per-chunk counters (192 blocks/chunk)
//   - GEMM launched concurrently (captured stream fork); each thread gates
//     its cp.async on ld.acquire of the chunk counter
//   - bounded spin + per-thread self-convert fallback => deadlock-impossible
// Pass 0 (concurrent): x|h -> A16[8192x2048], Wx|Wh -> B16[4096x2048] (RN).

#define B_DIM 8192
#define H_DIM 1024
#define KTOT  2048
#define BM 128
#define BK 64
#define A_STAGE 16384
#define B_STAGE 16384
#define STAGE_BYTES (A_STAGE + B_STAGE)        // 32768
#define STAGES 3
#define NSTG (KTOT / BK)                       // 32
#define SM_BIAS (STAGES * STAGE_BYTES)         // 98304
#define SM_MBAR (SM_BIAS + 512)                // full[3] @ +0, empty[3] @ +24
#define SM_CPREB (SM_MBAR + 48)                // c_prev-ready mbarrier
#define SM_CPRE (SM_MBAR + 128)                // c_prev tile 16KB
#define SMEM_TOTAL (SM_CPRE + 16384)           // 115328 (2 CTAs/SM)
#define CVT_BPC 192                            // cvt blocks per k-chunk

__device__ __align__(128) __half A16[(size_t)B_DIM * KTOT];   // 32 MB
__device__ __align__(128) __half B16[(size_t)4096 * KTOT];    // 16 MB
__device__ int g_cnt[32 * 32];                 // per-chunk counters, 128B apart

__device__ __forceinline__ uint32_t smem_u32(const void* p) {
    uint32_t a;
    asm("{ .reg .u64 t; cvta.to.shared.u64 t, %1; cvt.u32.u64 %0, t; }" : "=r"(a) : "l"(p));
    return a;
}
__device__ __forceinline__ void cp16(uint32_t dst, const void* src) {
    asm volatile("cp.async.cg.shared.global [%0], [%1], 16;" :: "r"(dst), "l"(src));
}
__device__ __forceinline__ uint32_t h2u(__half2 h) {
    return *reinterpret_cast<uint32_t*>(&h);
}
__device__ __forceinline__ void mbar_init(uint32_t a, uint32_t cnt) {
    asm volatile("mbarrier.init.shared.b64 [%0], %1;" :: "r"(a), "r"(cnt) : "memory");
}
__device__ __forceinline__ void mbar_wait(uint32_t a, uint32_t par) {
    asm volatile(
        "{\n\t.reg .pred P;\n"
        "WL%=:\n\t"
        "mbarrier.try_wait.parity.acquire.cta.shared::cta.b64 P, [%0], %1, 0x989680;\n\t"
        "@P bra WD%=;\n\t"
        "bra WL%=;\n"
        "WD%=:\n\t}"
        :: "r"(a), "r"(par) : "memory");
}
__device__ __forceinline__ void mbar_arrive(uint32_t a) {
    asm volatile("mbarrier.arrive.release.cta.shared::cta.b64 _, [%0];" :: "r"(a) : "memory");
}
__device__ __forceinline__ void cpasync_arrive(uint32_t a) {
    asm volatile("cp.async.mbarrier.arrive.noinc.shared::cta.b64 [%0];" :: "r"(a) : "memory");
}
__device__ __forceinline__ bool flag_ready(int k) {
    int v;
    asm volatile("ld.acquire.gpu.global.b32 %0, [%1];" : "=r"(v)
                 : "l"(&g_cnt[k * 32]) : "memory");
    return v >= CVT_BPC;
}
__device__ __forceinline__ uint4 cvt16(const float* s) {
    float4 v0 = ((const float4*)s)[0], v1 = ((const float4*)s)[1];
    uint4 u;
    u.x = h2u(__floats2half2_rn(v0.x, v0.y));
    u.y = h2u(__floats2half2_rn(v0.z, v0.w));
    u.z = h2u(__floats2half2_rn(v1.x, v1.y));
    u.w = h2u(__floats2half2_rn(v1.z, v1.w));
    return u;
}

// ---------------- Pass 0: fp32 -> fp16, k-major with completion counters ----
__global__ void __launch_bounds__(256) cvt_kernel(
    const float* __restrict__ x, const float* __restrict__ hp,
    const float* __restrict__ Wx, const float* __restrict__ Wh)
{
    const int chunk = blockIdx.x / CVT_BPC;
    const int s = (blockIdx.x % CVT_BPC) * 256 + threadIdx.x;  // 0..49151
    const float* src;
    __half* dst;
    if (s < 32768) {                       // A: row = s>>2, 16-elem quarter
        int row = s >> 2;
        int kk = chunk * 64 + (s & 3) * 16;
        src = (kk < 1024) ? x + (size_t)row * 1024 + kk
                          : hp + (size_t)row * 1024 + kk - 1024;
        dst = A16 + (size_t)row * 2048 + kk;
    } else {                               // B (weights)
        int t2 = s - 32768;
        int row = t2 >> 2;
        int kk = chunk * 64 + (t2 & 3) * 16;
        src = (kk < 1024) ? Wx + (size_t)row * 1024 + kk
                          : Wh + (size_t)row * 1024 + kk - 1024;
        dst = B16 + (size_t)row * 2048 + kk;
    }
    ((uint4*)dst)[0] = cvt16(src);
    ((uint4*)dst)[1] = cvt16(src + 8);
    __threadfence();
    __syncthreads();
    if (threadIdx.x == 0) atomicAdd(&g_cnt[chunk * 32], 1);
}

// ---------------- Pass 1: GEMM + fused LSTM --------------------------------
struct TileCtx {
    uint32_t sb;
    int m0, c0, tid, lane;
    int wm, wn;
    int a_row, a_kh, b_row, b_kh;
    float (*acc)[4][4];
    const float *xs, *hs, *wxs, *whs;      // fp32 sources for fallback
};

// Per-thread self-convert of exactly the bytes this thread's cp16s will read.
__device__ void fallback_convert(const TileCtx& t, int k) {
    const int k0 = k * BK;
    const float* asrc = (k0 < 1024) ? t.xs : t.hs;
    const float* bsrc = (k0 < 1024) ? t.wxs : t.whs;
    const int ko = k0 & 1023;
#pragma unroll
    for (int p = 0; p < 4; p++) {
        int ch = t.tid + p * 256;
        int row = ch >> 3, c = ch & 7;
        {
            const float* s = asrc + (size_t)(t.m0 + row) * 1024 + ko + c * 8;
            *(uint4*)(A16 + (size_t)(t.m0 + row) * 2048 + k0 + c * 8) = cvt16(s);
        }
        {
            int wrow = ((row >> 3) & 3) * 1024 + t.c0 + (row >> 5) * 8 + (row & 7);
            const float* s = bsrc + (size_t)wrow * 1024 + ko + c * 8;
            *(uint4*)(B16 + (size_t)wrow * 2048 + k0 + c * 8) = cvt16(s);
        }
    }
    __threadfence();
}

__device__ __forceinline__ void wait_chunk(const TileCtx& t, int k, bool& dead) {
    if (!dead) {
        if (flag_ready(k)) return;
        for (int it = 0; it < 200; ++it)
            if (flag_ready(k)) return;
        dead = true;   // cvt starved/slow: self-serve from here on (correct either way)
    }
    fallback_convert(t, k);
}

template <int LBUF>
__device__ __forceinline__ void issue_loads_A(const TileCtx& t, int kt) {
    const int k0 = kt * BK;
    const uint32_t abase = t.sb + LBUF * STAGE_BYTES;
#pragma unroll
    for (int p = 0; p < 4; p++) {
        int ch = t.tid + p * 256;
        int row = ch >> 3, c = ch & 7;
        cp16(abase + row * 128 + ((c ^ (row & 7)) << 4),
             A16 + (size_t)(t.m0 + row) * KTOT + k0 + c * 8);
    }
}
template <int LBUF>
__device__ __forceinline__ void issue_loads_B(const TileCtx& t, int kt) {
    const int k0 = kt * BK;
    const uint32_t bbase = t.sb + LBUF * STAGE_BYTES + A_STAGE;
#pragma unroll
    for (int p = 0; p < 4; p++) {
        int ch = t.tid + p * 256;
        int row = ch >> 3, c = ch & 7;
        int wrow = ((row >> 3) & 3) * 1024 + t.c0 + (row >> 5) * 8 + (row & 7);
        cp16(bbase + row * 128 + ((c ^ (row & 7)) << 4),
             B16 + (size_t)wrow * KTOT + k0 + c * 8);
    }
}
__device__ __forceinline__ void issue_loads_cprev(const TileCtx& t,
                                                  const float* __restrict__ c_prev) {
#pragma unroll
    for (int p = 0; p < 4; p++) {
        int ch = t.tid + p * 256;
        int row = ch >> 3, c = ch & 7;
        cp16(t.sb + SM_CPRE + row * 128 + ((c ^ (row & 7)) << 4),
             c_prev + (size_t)(t.m0 + row) * 1024 + t.c0 + c * 4);
    }
}

template <int BUF>
__device__ __forceinline__ void ldsm_ks(const TileCtx& t, int ks,
                                        uint32_t af[4][4], uint32_t bf[4][2]) {
    const uint32_t abuf = t.sb + BUF * STAGE_BYTES;
    const uint32_t bbuf = abuf + A_STAGE;
#pragma unroll
    for (int i = 0; i < 4; i++) {
        int ra = t.wm + i * 16 + t.a_row;
        int ck = ks * 2 + t.a_kh;
        uint32_t addr = abuf + ra * 128 + (((uint32_t)(ck ^ (ra & 7))) << 4);
        asm volatile(
            "ldmatrix.sync.aligned.m8n8.x4.shared.b16 {%0,%1,%2,%3}, [%4];"
            : "=r"(af[i][0]), "=r"(af[i][1]), "=r"(af[i][2]), "=r"(af[i][3])
            : "r"(addr));
    }
#pragma unroll
    for (int jp = 0; jp < 2; jp++) {
        int rn = t.wn + jp * 16 + t.b_row;
        int ck = ks * 2 + t.b_kh;
        uint32_t addr = bbuf + rn * 128 + (((uint32_t)(ck ^ (rn & 7))) << 4);
        asm volatile(
            "ldmatrix.sync.aligned.m8n8.x4.shared.b16 {%0,%1,%2,%3}, [%4];"
            : "=r"(bf[2 * jp][0]), "=r"(bf[2 * jp][1]),
              "=r"(bf[2 * jp + 1][0]), "=r"(bf[2 * jp + 1][1])
            : "r"(addr));
    }
}
__device__ __forceinline__ void mma_ks(const TileCtx& t,
                                       uint32_t af[4][4], uint32_t bf[4][2]) {
#pragma unroll
    for (int i = 0; i < 4; i++)
#pragma unroll
        for (int j = 0; j < 4; j++) {
            asm volatile(
                "mma.sync.aligned.m16n8k16.row.col.f32.f16.f16.f32 "
                "{%0,%1,%2,%3}, {%4,%5,%6,%7}, {%8,%9}, {%0,%1,%2,%3};"
                : "+f"(t.acc[i][j][0]), "+f"(t.acc[i][j][1]),
                  "+f"(t.acc[i][j][2]), "+f"(t.acc[i][j][3])
                : "r"(af[i][0]), "r"(af[i][1]), "r"(af[i][2]), "r"(af[i][3]),
                  "r"(bf[j][0]), "r"(bf[j][1]));
        }
}
template <int BUF>
__device__ __forceinline__ void compute_ks(const TileCtx& t, int ks) {
    uint32_t af[4][4], bf[4][2];
    ldsm_ks<BUF>(t, ks, af, bf);
    mma_ks(t, af, bf);
}

template <int BUF, bool LOAD, bool SKIP_EMPTY, bool ARRIVE>
__device__ __forceinline__ void tile_step(
    const TileCtx& t, int kt, uint32_t pf, uint32_t pe, bool& dead)
{
    constexpr int LBUF = (BUF + 2) % 3;
    mbar_wait(t.sb + SM_MBAR + BUF * 8, pf);
    compute_ks<BUF>(t, 0);
    if (LOAD) {
        wait_chunk(t, kt + 2, dead);
        if (!SKIP_EMPTY) mbar_wait(t.sb + SM_MBAR + 24 + LBUF * 8, pe);
        issue_loads_A<LBUF>(t, kt + 2);
    }
    compute_ks<BUF>(t, 1);
    if (LOAD) {
        issue_loads_B<LBUF>(t, kt + 2);
        cpasync_arrive(t.sb + SM_MBAR + LBUF * 8);
    }
    compute_ks<BUF>(t, 2);
    {
        uint32_t af[4][4], bf[4][2];
        ldsm_ks<BUF>(t, 3, af, bf);
        if (ARRIVE && t.lane == 0)
            mbar_arrive(t.sb + SM_MBAR + 24 + BUF * 8);
        mma_ks(t, af, bf);
    }
}

__device__ __forceinline__ float fsigm(float v) {
    return 1.0f / (1.0f + __expf(-v));
}
__device__ __forceinline__ float ftanh(float v) {
    float e = __expf(2.0f * fabsf(v));
    float r = 1.0f - 2.0f / (e + 1.0f);
    return copysignf(r, v);
}

__global__ void __launch_bounds__(256, 2) lstm_fused_kernel(
    const float* __restrict__ c_prev,
    const float* __restrict__ bx,
    const float* __restrict__ bh,
    float* __restrict__ out,
    const float* __restrict__ x,
    const float* __restrict__ hp,
    const float* __restrict__ Wx,
    const float* __restrict__ Wh)
{
    extern __shared__ char smem[];
    const uint32_t sb = smem_u32(smem);
    const int tid = threadIdx.x;
    const int warp = tid >> 5, lane = tid & 31;

    TileCtx t;
    t.sb = sb;
    t.tid = tid;
    t.lane = lane;
    t.wm = (warp >> 2) * 64;
    t.wn = (warp & 3) * 32;
    t.m0 = blockIdx.y * BM;
    t.c0 = blockIdx.x * 32;
    t.a_row = ((lane >> 3) & 1) * 8 + (lane & 7);
    t.a_kh  = lane >> 4;
    t.b_row = ((lane >> 4) & 1) * 8 + (lane & 7);
    t.b_kh  = (lane >> 3) & 1;
    t.xs = x; t.hs = hp; t.wxs = Wx; t.whs = Wh;

    if (tid == 0) {
#pragma unroll
        for (int s = 0; s < 3; s++) {
            mbar_init(sb + SM_MBAR + s * 8, 256);       // full[s]
            mbar_init(sb + SM_MBAR + 24 + s * 8, 8);    // empty[s]
        }
        mbar_init(sb + SM_CPREB, 256);                  // c_prev ready
    }
    if (tid < 128) {
        int g = tid >> 5, col = tid & 31;
        ((float*)(smem + SM_BIAS))[tid] =
            bx[g * 1024 + t.c0 + col] + bh[g * 1024 + t.c0 + col];
    }

    float acc[4][4][4];
#pragma unroll
    for (int i = 0; i < 4; i++)
#pragma unroll
        for (int j = 0; j < 4; j++)
#pragma unroll
            for (int r = 0; r < 4; r++) acc[i][j][r] = 0.f;
    t.acc = acc;

    bool dead = false;
    __syncthreads();   // mbarrier init + bias visible before any arrives

    // prologue: stages 0,1 gated on cvt chunk flags; c_prev last.
    wait_chunk(t, 0, dead);
    issue_loads_A<0>(t, 0);
    issue_loads_B<0>(t, 0);
    cpasync_arrive(sb + SM_MBAR + 0 * 8);
    wait_chunk(t, 1, dead);
    issue_loads_A<1>(t, 1);
    issue_loads_B<1>(t, 1);
    cpasync_arrive(sb + SM_MBAR + 1 * 8);
    issue_loads_cprev(t, c_prev);
    cpasync_arrive(sb + SM_CPREB);

    uint32_t pf = 0;
    tile_step<0, true, true,  true>(t, 0, pf, 0, dead);
    tile_step<1, true, false, true>(t, 1, pf, pf, dead);
    tile_step<2, true, false, true>(t, 2, pf, pf, dead);
    pf ^= 1;
    for (int m = 1; m < 10; m++) {
        tile_step<0, true, false, true>(t, 3 * m,     pf, pf ^ 1, dead);
        tile_step<1, true, false, true>(t, 3 * m + 1, pf, pf, dead);
        tile_step<2, true, false, true>(t, 3 * m + 2, pf, pf, dead);
        pf ^= 1;
    }
    tile_step<0, false, false, false>(t, 30, pf, 0, dead);
    tile_step<1, false, false, false>(t, 31, pf, 0, dead);

    // ---- fused LSTM epilogue (c_prev from smem) ----
    mbar_wait(sb + SM_CPREB, 0);

    const float* bs = (const float*)(smem + SM_BIAS);
    const size_t oh_off = (size_t)B_DIM * H_DIM;
    const int bcol = (warp & 3) * 8 + 2 * (lane & 3);
    const int hc_col = t.c0 + bcol;
    const int cp_chunk = 2 * (warp & 3) + ((lane & 3) >> 1);
    const int cp_byte  = 8 * ((lane & 3) & 1);

    const float b_i0 = bs[0 * 32 + bcol], b_i1 = bs[0 * 32 + bcol + 1];
    const float b_f0 = bs[1 * 32 + bcol], b_f1 = bs[1 * 32 + bcol + 1];
    const float b_o0 = bs[2 * 32 + bcol], b_o1 = bs[2 * 32 + bcol + 1];
    const float b_g0 = bs[3 * 32 + bcol], b_g1 = bs[3 * 32 + bcol + 1];

#pragma unroll
    for (int i = 0; i < 4; i++) {
        const int lrow0 = t.wm + i * 16 + (lane >> 2);
#pragma unroll
        for (int tt = 0; tt < 2; tt++) {
            const int lrow = lrow0 + tt * 8;
            const int row = t.m0 + lrow;
            const int k0 = tt * 2;
            float2 cp = *(const float2*)(smem + SM_CPRE + lrow * 128 +
                                         ((cp_chunk ^ (lrow & 7)) << 4) + cp_byte);

            float iv0 = acc[i][0][k0]     + b_i0;
            float iv1 = acc[i][0][k0 + 1] + b_i1;
            float fv0 = acc[i][1][k0]     + b_f0;
            float fv1 = acc[i][1][k0 + 1] + b_f1;
            float ov0 = acc[i][2][k0]     + b_o0;
            float ov1 = acc[i][2][k0 + 1] + b_o1;
            float gv0 = acc[i][3][k0]     + b_g0;
            float gv1 = acc[i][3][k0 + 1] + b_g1;

            float ig0 = fsigm(iv0), ig1 = fsigm(iv1);
            float fg0 = fsigm(fv0), fg1 = fsigm(fv1);
            float og0 = fsigm(ov0), og1 = fsigm(ov1);
            float gg0 = ftanh(gv0), gg1 = ftanh(gv1);

            float cv0 = fg0 * cp.x + ig0 * gg0;
            float cv1 = fg1 * cp.y + ig1 * gg1;
            float hv0 = og0 * ftanh(cv0);
            float hv1 = og1 * ftanh(cv1);

            *(float2*)(out + (size_t)row * 1024 + hc_col) = make_float2(cv0, cv1);
            *(float2*)(out + oh_off + (size_t)row * 1024 + hc_col) = make_float2(hv0, hv1);
        }
    }
}

extern "C" void kernel_launch(void* const* d_in, const int* in_sizes, int n_in,
                              void* d_out, int out_size) {
    const float* x      = (const float*)d_in[0];
    const float* c_prev = (const float*)d_in[1];
    const float* h_prev = (const float*)d_in[2];
    const float* Wx     = (const float*)d_in[3];
    const float* bx     = (const float*)d_in[4];
    const float* Wh     = (const float*)d_in[5];
    const float* bh     = (const float*)d_in[6];
    float* out = (float*)d_out;

    static cudaStream_t s2 = nullptr;
    static cudaEvent_t eF = nullptr, eJ = nullptr;
    if (!s2) {
        cudaStreamCreateWithFlags(&s2, cudaStreamNonBlocking);
        cudaEventCreateWithFlags(&eF, cudaEventDisableTiming);
        cudaEventCreateWithFlags(&eJ, cudaEventDisableTiming);
    }
    cudaFuncSetAttribute(lstm_fused_kernel,
                         cudaFuncAttributeMaxDynamicSharedMemorySize, SMEM_TOTAL);

    // reset chunk counters, then fork: cvt on s2 concurrent with GEMM on 0.
    void* cntp = nullptr;
    cudaGetSymbolAddress(&cntp, g_cnt);
    cudaMemsetAsync(cntp, 0, sizeof(int) * 32 * 32, 0);
    cudaEventRecord(eF, 0);
    cudaStreamWaitEvent(s2, eF, 0);
    cvt_kernel<<<32 * CVT_BPC, 256, 0, s2>>>(x, h_prev, Wx, Wh);

    dim3 grid(H_DIM / 32, B_DIM / BM);  // (32, 64)
    lstm_fused_kernel<<<grid, 256, SMEM_TOTAL>>>(c_prev, bx, bh, out,
                                                 x, h_prev, Wx, Wh);
    cudaEventRecord(eJ, s2);
    cudaStreamWaitEvent(0, eJ, 0);
}

// round 14
// speedup vs baseline: 1.1870x; 1.1870x over previous
#include <cuda_runtime.h>
#include <cuda_fp16.h>
#include <math.h>
#include <stdint.h>

// Fused LSTM cell, fp16 mma.sync m16n8k16 (f32 accum) + ldmatrix.
// R14 = R12 chassis (proven fastest: 128x128 CTA, 8 warps 64x32, 3-stage
//       mbarrier ring, 2 CTAs/SM, c_prev smem prefetch) + cache-policy
//       hints only: __ldcs on cvt sources (read-once), __stcs on out
//       (write-once) to preserve B16 residency in L2 across CTA waves.
// Pass 0: convert x|h -> A16[8192x2048], Wx|Wh -> B16[4096x2048] (RN).

#define B_DIM 8192
#define H_DIM 1024
#define KTOT  2048
#define BM 128
#define BK 64
#define A_STAGE 16384
#define B_STAGE 16384
#define STAGE_BYTES (A_STAGE + B_STAGE)        // 32768
#define STAGES 3
#define NSTG (KTOT / BK)                       // 32
#define SM_BIAS (STAGES * STAGE_BYTES)         // 98304
#define SM_MBAR (SM_BIAS + 512)                // full[3] @ +0, empty[3] @ +24
#define SM_CPREB (SM_MBAR + 48)                // c_prev-ready mbarrier
#define SM_CPRE (SM_MBAR + 128)                // c_prev tile 16KB
#define SMEM_TOTAL (SM_CPRE + 16384)           // 115328 (2 CTAs/SM)

__device__ __align__(128) __half A16[(size_t)B_DIM * KTOT];   // 32 MB
__device__ __align__(128) __half B16[(size_t)4096 * KTOT];    // 16 MB

__device__ __forceinline__ uint32_t smem_u32(const void* p) {
    uint32_t a;
    asm("{ .reg .u64 t; cvta.to.shared.u64 t, %1; cvt.u32.u64 %0, t; }" : "=r"(a) : "l"(p));
    return a;
}
__device__ __forceinline__ void cp16(uint32_t dst, const void* src) {
    asm volatile("cp.async.cg.shared.global [%0], [%1], 16;" :: "r"(dst), "l"(src));
}
__device__ __forceinline__ uint32_t h2u(__half2 h) {
    return *reinterpret_cast<uint32_t*>(&h);
}
__device__ __forceinline__ void mbar_init(uint32_t a, uint32_t cnt) {
    asm volatile("mbarrier.init.shared.b64 [%0], %1;" :: "r"(a), "r"(cnt) : "memory");
}
__device__ __forceinline__ void mbar_wait(uint32_t a, uint32_t par) {
    asm volatile(
        "{\n\t.reg .pred P;\n"
        "WL%=:\n\t"
        "mbarrier.try_wait.parity.acquire.cta.shared::cta.b64 P, [%0], %1, 0x989680;\n\t"
        "@P bra WD%=;\n\t"
        "bra WL%=;\n"
        "WD%=:\n\t}"
        :: "r"(a), "r"(par) : "memory");
}
__device__ __forceinline__ void mbar_arrive(uint32_t a) {
    asm volatile("mbarrier.arrive.release.cta.shared::cta.b64 _, [%0];" :: "r"(a) : "memory");
}
__device__ __forceinline__ void cpasync_arrive(uint32_t a) {
    asm volatile("cp.async.mbarrier.arrive.noinc.shared::cta.b64 [%0];" :: "r"(a) : "memory");
}

// ---------------- Pass 0: fp32 -> fp16 conversion (K-concatenated) ----------
__global__ void __launch_bounds__(256) cvt_kernel(
    const float* __restrict__ x, const float* __restrict__ hp,
    const float* __restrict__ Wx, const float* __restrict__ Wh)
{
    size_t t = (size_t)blockIdx.x * 256 + threadIdx.x;
    const size_t NA = (size_t)B_DIM * KTOT / 8;
    const float* src;
    __half* dst;
    if (t < NA) {
        size_t e = t * 8;
        int b = (int)(e >> 11), k = (int)(e & 2047);
        src = (k < 1024) ? x + (size_t)b * 1024 + k
                         : hp + (size_t)b * 1024 + (k - 1024);
        dst = A16 + e;
    } else {
        size_t e = (t - NA) * 8;
        int n = (int)(e >> 11), k = (int)(e & 2047);
        src = (k < 1024) ? Wx + (size_t)n * 1024 + k
                         : Wh + (size_t)n * 1024 + (k - 1024);
        dst = B16 + e;
    }
    float4 v0 = __ldcs((const float4*)src);        // read-once: evict-first
    float4 v1 = __ldcs((const float4*)(src + 4));
    uint4 u;
    u.x = h2u(__floats2half2_rn(v0.x, v0.y));
    u.y = h2u(__floats2half2_rn(v0.z, v0.w));
    u.z = h2u(__floats2half2_rn(v1.x, v1.y));
    u.w = h2u(__floats2half2_rn(v1.z, v1.w));
    *(uint4*)dst = u;
}

// ---------------- Pass 1: GEMM + fused LSTM --------------------------------
struct TileCtx {
    uint32_t sb;
    int m0, c0, tid, lane;
    int wm, wn;
    int a_row, a_kh, b_row, b_kh;
    float (*acc)[4][4];
};

template <int LBUF>
__device__ __forceinline__ void issue_loads_A(const TileCtx& t, int kt) {
    const int k0 = kt * BK;
    const uint32_t abase = t.sb + LBUF * STAGE_BYTES;
#pragma unroll
    for (int p = 0; p < 4; p++) {
        int ch = t.tid + p * 256;
        int row = ch >> 3, c = ch & 7;
        cp16(abase + row * 128 + ((c ^ (row & 7)) << 4),
             A16 + (size_t)(t.m0 + row) * KTOT + k0 + c * 8);
    }
}
template <int LBUF>
__device__ __forceinline__ void issue_loads_B(const TileCtx& t, int kt) {
    const int k0 = kt * BK;
    const uint32_t bbase = t.sb + LBUF * STAGE_BYTES + A_STAGE;
#pragma unroll
    for (int p = 0; p < 4; p++) {
        int ch = t.tid + p * 256;
        int row = ch >> 3, c = ch & 7;
        int wrow = ((row >> 3) & 3) * 1024 + t.c0 + (row >> 5) * 8 + (row & 7);
        cp16(bbase + row * 128 + ((c ^ (row & 7)) << 4),
             B16 + (size_t)wrow * KTOT + k0 + c * 8);
    }
}
// c_prev tile [128 x 32] f32, swizzled 16B chunks, 16KB.
__device__ __forceinline__ void issue_loads_cprev(const TileCtx& t,
                                                  const float* __restrict__ c_prev) {
#pragma unroll
    for (int p = 0; p < 4; p++) {
        int ch = t.tid + p * 256;
        int row = ch >> 3, c = ch & 7;
        cp16(t.sb + SM_CPRE + row * 128 + ((c ^ (row & 7)) << 4),
             c_prev + (size_t)(t.m0 + row) * 1024 + t.c0 + c * 4);
    }
}

template <int BUF>
__device__ __forceinline__ void ldsm_ks(const TileCtx& t, int ks,
                                        uint32_t af[4][4], uint32_t bf[4][2]) {
    const uint32_t abuf = t.sb + BUF * STAGE_BYTES;
    const uint32_t bbuf = abuf + A_STAGE;
#pragma unroll
    for (int i = 0; i < 4; i++) {
        int ra = t.wm + i * 16 + t.a_row;
        int ck = ks * 2 + t.a_kh;
        uint32_t addr = abuf + ra * 128 + (((uint32_t)(ck ^ (ra & 7))) << 4);
        asm volatile(
            "ldmatrix.sync.aligned.m8n8.x4.shared.b16 {%0,%1,%2,%3}, [%4];"
            : "=r"(af[i][0]), "=r"(af[i][1]), "=r"(af[i][2]), "=r"(af[i][3])
            : "r"(addr));
    }
#pragma unroll
    for (int jp = 0; jp < 2; jp++) {
        int rn = t.wn + jp * 16 + t.b_row;
        int ck = ks * 2 + t.b_kh;
        uint32_t addr = bbuf + rn * 128 + (((uint32_t)(ck ^ (rn & 7))) << 4);
        asm volatile(
            "ldmatrix.sync.aligned.m8n8.x4.shared.b16 {%0,%1,%2,%3}, [%4];"
            : "=r"(bf[2 * jp][0]), "=r"(bf[2 * jp][1]),
              "=r"(bf[2 * jp + 1][0]), "=r"(bf[2 * jp + 1][1])
            : "r"(addr));
    }
}
__device__ __forceinline__ void mma_ks(const TileCtx& t,
                                       uint32_t af[4][4], uint32_t bf[4][2]) {
#pragma unroll
    for (int i = 0; i < 4; i++)
#pragma unroll
        for (int j = 0; j < 4; j++) {
            asm volatile(
                "mma.sync.aligned.m16n8k16.row.col.f32.f16.f16.f32 "
                "{%0,%1,%2,%3}, {%4,%5,%6,%7}, {%8,%9}, {%0,%1,%2,%3};"
                : "+f"(t.acc[i][j][0]), "+f"(t.acc[i][j][1]),
                  "+f"(t.acc[i][j][2]), "+f"(t.acc[i][j][3])
                : "r"(af[i][0]), "r"(af[i][1]), "r"(af[i][2]), "r"(af[i][3]),
                  "r"(bf[j][0]), "r"(bf[j][1]));
        }
}
template <int BUF>
__device__ __forceinline__ void compute_ks(const TileCtx& t, int ks) {
    uint32_t af[4][4], bf[4][2];
    ldsm_ks<BUF>(t, ks, af, bf);
    mma_ks(t, af, bf);
}

// R8/R12 ordering: full-wait first, loads interleaved between ks steps,
// early empty-release after the tile's last LDSM.
template <int BUF, bool LOAD, bool SKIP_EMPTY, bool ARRIVE>
__device__ __forceinline__ void tile_step(
    const TileCtx& t, int kt, uint32_t pf, uint32_t pe)
{
    constexpr int LBUF = (BUF + 2) % 3;
    mbar_wait(t.sb + SM_MBAR + BUF * 8, pf);
    compute_ks<BUF>(t, 0);
    if (LOAD) {
        if (!SKIP_EMPTY) mbar_wait(t.sb + SM_MBAR + 24 + LBUF * 8, pe);
        issue_loads_A<LBUF>(t, kt + 2);
    }
    compute_ks<BUF>(t, 1);
    if (LOAD) {
        issue_loads_B<LBUF>(t, kt + 2);
        cpasync_arrive(t.sb + SM_MBAR + LBUF * 8);
    }
    compute_ks<BUF>(t, 2);
    {
        uint32_t af[4][4], bf[4][2];
        ldsm_ks<BUF>(t, 3, af, bf);
        if (ARRIVE && t.lane == 0)
            mbar_arrive(t.sb + SM_MBAR + 24 + BUF * 8);
        mma_ks(t, af, bf);
    }
}

__device__ __forceinline__ float fsigm(float v) {
    return 1.0f / (1.0f + __expf(-v));
}
__device__ __forceinline__ float ftanh(float v) {
    float e = __expf(2.0f * fabsf(v));
    float r = 1.0f - 2.0f / (e + 1.0f);
    return copysignf(r, v);
}

__global__ void __launch_bounds__(256, 2) lstm_fused_kernel(
    const float* __restrict__ c_prev,
    const float* __restrict__ bx,
    const float* __restrict__ bh,
    float* __restrict__ out)
{
    extern __shared__ char smem[];
    const uint32_t sb = smem_u32(smem);
    const int tid = threadIdx.x;
    const int warp = tid >> 5, lane = tid & 31;

    TileCtx t;
    t.sb = sb;
    t.tid = tid;
    t.lane = lane;
    t.wm = (warp >> 2) * 64;
    t.wn = (warp & 3) * 32;
    t.m0 = blockIdx.y * BM;
    t.c0 = blockIdx.x * 32;
    t.a_row = ((lane >> 3) & 1) * 8 + (lane & 7);
    t.a_kh  = lane >> 4;
    t.b_row = ((lane >> 4) & 1) * 8 + (lane & 7);
    t.b_kh  = (lane >> 3) & 1;

    if (tid == 0) {
#pragma unroll
        for (int s = 0; s < 3; s++) {
            mbar_init(sb + SM_MBAR + s * 8, 256);       // full[s]
            mbar_init(sb + SM_MBAR + 24 + s * 8, 8);    // empty[s]
        }
        mbar_init(sb + SM_CPREB, 256);                  // c_prev ready
    }
    if (tid < 128) {
        int g = tid >> 5, col = tid & 31;
        ((float*)(smem + SM_BIAS))[tid] =
            bx[g * 1024 + t.c0 + col] + bh[g * 1024 + t.c0 + col];
    }

    float acc[4][4][4];
#pragma unroll
    for (int i = 0; i < 4; i++)
#pragma unroll
        for (int j = 0; j < 4; j++)
#pragma unroll
            for (int r = 0; r < 4; r++) acc[i][j][r] = 0.f;
    t.acc = acc;

    __syncthreads();   // mbarrier init + bias visible before any arrives

    // prologue: stage 0, stage 1, then c_prev.
    issue_loads_A<0>(t, 0);
    issue_loads_B<0>(t, 0);
    cpasync_arrive(sb + SM_MBAR + 0 * 8);
    issue_loads_A<1>(t, 1);
    issue_loads_B<1>(t, 1);
    cpasync_arrive(sb + SM_MBAR + 1 * 8);
    issue_loads_cprev(t, c_prev);
    cpasync_arrive(sb + SM_CPREB);

    uint32_t pf = 0;
    tile_step<0, true, true,  true>(t, 0, pf, 0);
    tile_step<1, true, false, true>(t, 1, pf, pf);
    tile_step<2, true, false, true>(t, 2, pf, pf);
    pf ^= 1;
    for (int m = 1; m < 10; m++) {
        tile_step<0, true, false, true>(t, 3 * m,     pf, pf ^ 1);
        tile_step<1, true, false, true>(t, 3 * m + 1, pf, pf);
        tile_step<2, true, false, true>(t, 3 * m + 2, pf, pf);
        pf ^= 1;
    }
    tile_step<0, false, false, false>(t, 30, pf, 0);
    tile_step<1, false, false, false>(t, 31, pf, 0);

    // ---- fused LSTM epilogue (c_prev from smem, streaming out stores) ----
    mbar_wait(sb + SM_CPREB, 0);

    const float* bs = (const float*)(smem + SM_BIAS);
    const size_t oh_off = (size_t)B_DIM * H_DIM;
    const int bcol = (warp & 3) * 8 + 2 * (lane & 3);
    const int hc_col = t.c0 + bcol;
    const int cp_chunk = 2 * (warp & 3) + ((lane & 3) >> 1);
    const int cp_byte  = 8 * ((lane & 3) & 1);

    const float b_i0 = bs[0 * 32 + bcol], b_i1 = bs[0 * 32 + bcol + 1];
    const float b_f0 = bs[1 * 32 + bcol], b_f1 = bs[1 * 32 + bcol + 1];
    const float b_o0 = bs[2 * 32 + bcol], b_o1 = bs[2 * 32 + bcol + 1];
    const float b_g0 = bs[3 * 32 + bcol], b_g1 = bs[3 * 32 + bcol + 1];

#pragma unroll
    for (int i = 0; i < 4; i++) {
        const int lrow0 = t.wm + i * 16 + (lane >> 2);
#pragma unroll
        for (int tt = 0; tt < 2; tt++) {
            const int lrow = lrow0 + tt * 8;
            const int row = t.m0 + lrow;
            const int k0 = tt * 2;
            float2 cp = *(const float2*)(smem + SM_CPRE + lrow * 128 +
                                         ((cp_chunk ^ (lrow & 7)) << 4) + cp_byte);

            float iv0 = acc[i][0][k0]     + b_i0;
            float iv1 = acc[i][0][k0 + 1] + b_i1;
            float fv0 = acc[i][1][k0]     + b_f0;
            float fv1 = acc[i][1][k0 + 1] + b_f1;
            float ov0 = acc[i][2][k0]     + b_o0;
            float ov1 = acc[i][2][k0 + 1] + b_o1;
            float gv0 = acc[i][3][k0]     + b_g0;
            float gv1 = acc[i][3][k0 + 1] + b_g1;

            float ig0 = fsigm(iv0), ig1 = fsigm(iv1);
            float fg0 = fsigm(fv0), fg1 = fsigm(fv1);
            float og0 = fsigm(ov0), og1 = fsigm(ov1);
            float gg0 = ftanh(gv0), gg1 = ftanh(gv1);

            float cv0 = fg0 * cp.x + ig0 * gg0;
            float cv1 = fg1 * cp.y + ig1 * gg1;
            float hv0 = og0 * ftanh(cv0);
            float hv1 = og1 * ftanh(cv1);

            __stcs((float2*)(out + (size_t)row * 1024 + hc_col),
                   make_float2(cv0, cv1));
            __stcs((float2*)(out + oh_off + (size_t)row * 1024 + hc_col),
                   make_float2(hv0, hv1));
        }
    }
}

extern "C" void kernel_launch(void* const* d_in, const int* in_sizes, int n_in,
                              void* d_out, int out_size) {
    const float* x      = (const float*)d_in[0];
    const float* c_prev = (const float*)d_in[1];
    const float* h_prev = (const float*)d_in[2];
    const float* Wx     = (const float*)d_in[3];
    const float* bx     = (const float*)d_in[4];
    const float* Wh     = (const float*)d_in[5];
    const float* bh     = (const float*)d_in[6];
    float* out = (float*)d_out;

    cvt_kernel<<<12288, 256>>>(x, h_prev, Wx, Wh);

    cudaFuncSetAttribute(lstm_fused_kernel,
                         cudaFuncAttributeMaxDynamicSharedMemorySize, SMEM_TOTAL);
    dim3 grid(H_DIM / 32, B_DIM / BM);  // (32, 64)
    lstm_fused_kernel<<<grid, 256, SMEM_TOTAL>>>(c_prev, bx, bh, out);
}